// round 16
// baseline (speedup 1.0000x reference)
#include <cuda_runtime.h>
#include <cuda_fp16.h>
#include <cstdint>
#include <math.h>

// Problem constants
#define BBX 4
#define LLX 4096
#define CCX 512
#define HHX 16
#define HDX 32
#define KWX 13
#define KHX 6
#define NRPBX 25
#define MLX (BBX*LLX)          // 16384
#define KK  512

// ---------------------------------------------------------------------------
// Global scratch
// ---------------------------------------------------------------------------
__device__ __half g_qkvh[(size_t)MLX * (3 * CCX)];     // qkv fp16
__device__ __half g_at[(size_t)MLX * CCX];             // attn out fp16
__device__ __half g_w1[(size_t)(3*CCX) * CCX];         // qkv_w^T [1536,512] fp16
__device__ __half g_w2[(size_t)CCX * CCX];             // proj_w^T [512,512] fp16

// ---------------------------------------------------------------------------
// Helpers
// ---------------------------------------------------------------------------
__device__ __forceinline__ uint32_t sptr(const void* p) {
    return (uint32_t)__cvta_generic_to_shared(p);
}
__device__ __forceinline__ void cp16(uint32_t s, const void* g) {
    asm volatile("cp.async.cg.shared.global [%0], [%1], 16;\n" :: "r"(s), "l"(g));
}
__device__ __forceinline__ void cp_commit() {
    asm volatile("cp.async.commit_group;\n" ::: "memory");
}
__device__ __forceinline__ void cp_wait0() {
    asm volatile("cp.async.wait_group 0;\n" ::: "memory");
}
__device__ __forceinline__ void cp_wait1() {
    asm volatile("cp.async.wait_group 1;\n" ::: "memory");
}
__device__ __forceinline__ void mma_f16(float* c, const uint32_t* a, const uint32_t* b) {
    asm volatile(
        "mma.sync.aligned.m16n8k16.row.col.f32.f16.f16.f32 "
        "{%0,%1,%2,%3}, {%4,%5,%6,%7}, {%8,%9}, {%0,%1,%2,%3};\n"
        : "+f"(c[0]), "+f"(c[1]), "+f"(c[2]), "+f"(c[3])
        : "r"(a[0]), "r"(a[1]), "r"(a[2]), "r"(a[3]), "r"(b[0]), "r"(b[1]));
}
__device__ __forceinline__ uint32_t f2h2(float2 v) {
    __half2 h = __floats2half2_rn(v.x, v.y);
    return *(uint32_t*)&h;
}

// ---------------------------------------------------------------------------
// GEMM1: C[M,1536] = x_fp32[M,512] x (B_fp16[1536,512])^T + bias -> fp16 out
// A staged fp32 in smem (stride 288 B), converted to fp16 in FLOADA.
// 128x128 CTA, 128 thr (4 warps 2x2, warp tile 64x64), BK=64, 2-stage ring.
// ---------------------------------------------------------------------------
#define RBA  288u                    // fp32 A row stride bytes (256 + 32 pad)
#define RBYTES 144u                  // fp16 row stride (128 + 16 pad)
#define TILE_A32 (128u * RBA)        // 36864 B
#define TILE_B16 (128u * RBYTES)     // 18432 B
#define STAGE1_B (TILE_A32 + TILE_B16)  // 55296 B
#define SMEM1 (2u * STAGE1_B)        // 110592 B

__global__ __launch_bounds__(128, 2)
void gemm1_f32a(const float* __restrict__ A, const __half* __restrict__ B,
                const float* __restrict__ bias, __half* __restrict__ C, int N)
{
    extern __shared__ char smem[];

    const int tid  = threadIdx.x;
    const int warp = tid >> 5;
    const int lane = tid & 31;
    const int wm   = warp & 1;
    const int wn   = warp >> 1;
    const int gid  = lane >> 2;
    const int tg   = lane & 3;

    const int bm0 = blockIdx.y * 128;
    const int bn0 = blockIdx.x * 128;

    const float*  t0 = A + (size_t)bm0 * KK;
    const __half* t1 = B + (size_t)bn0 * KK;
    const uint32_t sbase = sptr(smem);

    // A: chunk = 64 fp32 = 256 B/row -> 16 cp16/row, 2048 units
    // B: 128 B/row -> 8 cp16/row, 1024 units. 24 per thread total.
    #define LOADCHUNK1(c, bufb) do { \
        const uint32_t sm0 = sbase + (bufb) * STAGE1_B; \
        const float*  gp0 = t0 + (c) * 64; \
        const __half* gp1 = t1 + (c) * 64; \
        _Pragma("unroll") \
        for (int i_ = 0; i_ < 16; i_++) { \
            int u_ = i_ * 128 + tid; \
            int row_ = u_ >> 4; \
            int c16_ = u_ & 15; \
            cp16(sm0 + (uint32_t)(row_ * RBA + c16_ * 16), \
                 gp0 + (size_t)row_ * KK + c16_ * 4); \
        } \
        _Pragma("unroll") \
        for (int i_ = 0; i_ < 8; i_++) { \
            int u_ = i_ * 128 + tid; \
            int row_ = u_ >> 3; \
            int c16_ = u_ & 7; \
            cp16(sm0 + TILE_A32 + (uint32_t)(row_ * RBYTES + c16_ * 16), \
                 gp1 + (size_t)row_ * KK + c16_ * 8); \
        } \
        cp_commit(); \
    } while (0)

    #define FLOADB1(s, ksv) do { \
        _Pragma("unroll") \
        for (int nt_ = 0; nt_ < 8; nt_++) { \
            const int col_ = wn * 64 + nt_ * 8 + gid; \
            const int o_ = col_ * (int)RBYTES + (ksv) * 32 + tg * 4; \
            bv[s][nt_][0] = *(const uint32_t*)(pB + o_); \
            bv[s][nt_][1] = *(const uint32_t*)(pB + o_ + 16); \
        } \
    } while (0)
    // A fragments: load fp32 pairs, convert to half2 regs
    #define FLOADA1(s, ksv) do { \
        _Pragma("unroll") \
        for (int mt_ = 0; mt_ < 4; mt_++) { \
            const int r0_ = (wm * 64 + mt_ * 16 + gid) * (int)RBA + (ksv) * 64 + tg * 8; \
            const int r1_ = r0_ + 8 * (int)RBA; \
            av[s][mt_][0] = f2h2(*(const float2*)(pA + r0_)); \
            av[s][mt_][1] = f2h2(*(const float2*)(pA + r1_)); \
            av[s][mt_][2] = f2h2(*(const float2*)(pA + r0_ + 32)); \
            av[s][mt_][3] = f2h2(*(const float2*)(pA + r1_ + 32)); \
        } \
    } while (0)

    float acc[4][8][4];
    #pragma unroll
    for (int mt = 0; mt < 4; mt++)
        #pragma unroll
        for (int nt = 0; nt < 8; nt++)
            #pragma unroll
            for (int c = 0; c < 4; c++) acc[mt][nt][c] = 0.f;

    const int nT = KK / 64;          // 8 chunks

    LOADCHUNK1(0, 0);

    for (int t = 0; t < nT; t++) {
        if (t + 1 < nT) LOADCHUNK1(t + 1, (t + 1) & 1);
        if (t + 1 < nT) cp_wait1(); else cp_wait0();
        __syncthreads();

        const char* stage = smem + (uint32_t)(t & 1) * STAGE1_B;
        const char* pA = stage;
        const char* pB = stage + TILE_A32;

        uint32_t av[2][4][4];
        uint32_t bv[2][8][2];

        FLOADB1(0, 0);
        FLOADA1(0, 0);
        #pragma unroll
        for (int ks = 0; ks < 4; ks++) {
            const int cs = ks & 1;
            if (ks < 3) {
                FLOADB1(cs ^ 1, ks + 1);
                FLOADA1(cs ^ 1, ks + 1);
            }
            #pragma unroll
            for (int mt = 0; mt < 4; mt++)
                #pragma unroll
                for (int nt = 0; nt < 8; nt++)
                    mma_f16(acc[mt][nt], av[cs][mt], bv[cs][nt]);
        }
        __syncthreads();
    }
    #undef LOADCHUNK1
    #undef FLOADA1
    #undef FLOADB1

    // epilogue: fp16 output
    #pragma unroll
    for (int nt = 0; nt < 8; nt++) {
        const int col = bn0 + wn * 64 + nt * 8 + tg * 2;
        const float2 bvv = *(const float2*)(bias + col);
        #pragma unroll
        for (int mt = 0; mt < 4; mt++) {
            const int r0 = bm0 + wm * 64 + mt * 16 + gid;
            __half2 h0 = __floats2half2_rn(acc[mt][nt][0] + bvv.x, acc[mt][nt][1] + bvv.y);
            __half2 h1 = __floats2half2_rn(acc[mt][nt][2] + bvv.x, acc[mt][nt][3] + bvv.y);
            *(__half2*)(C + (size_t)r0 * N + col)       = h0;
            *(__half2*)(C + (size_t)(r0 + 8) * N + col) = h1;
        }
    }
}

// ---------------------------------------------------------------------------
// GEMM2 (R13 config, unchanged): C_fp32 = A_fp16 x B_fp16^T + bias
// ---------------------------------------------------------------------------
#define TILE_B (128u * RBYTES)       // 18432 B
#define STAGE_B (2u * TILE_B)        // 36864 B
#define GEMM_SMEM (2u * STAGE_B)     // 73728 B

__global__ __launch_bounds__(128, 2)
void fp16_gemm_f32out(const __half* __restrict__ A, const __half* __restrict__ B,
                      const float* __restrict__ bias, float* __restrict__ C, int N)
{
    extern __shared__ char smem[];

    const int tid  = threadIdx.x;
    const int warp = tid >> 5;
    const int lane = tid & 31;
    const int wm   = warp & 1;
    const int wn   = warp >> 1;
    const int gid  = lane >> 2;
    const int tg   = lane & 3;

    const int bm0 = blockIdx.y * 128;
    const int bn0 = blockIdx.x * 128;

    const __half* t0 = A + (size_t)bm0 * KK;
    const __half* t1 = B + (size_t)bn0 * KK;
    const uint32_t sbase = sptr(smem);

    #define LOADCHUNK(c, bufb) do { \
        const uint32_t sm0 = sbase + (bufb) * STAGE_B; \
        const __half* gp0 = t0 + (c) * 64; \
        const __half* gp1 = t1 + (c) * 64; \
        _Pragma("unroll") \
        for (int i_ = 0; i_ < 8; i_++) { \
            int u_ = i_ * 128 + tid; \
            int row_ = u_ >> 3; \
            int c16_ = u_ & 7; \
            uint32_t so_ = (uint32_t)(row_ * RBYTES + c16_ * 16); \
            size_t go_ = (size_t)row_ * KK + c16_ * 8; \
            cp16(sm0 + so_,          gp0 + go_); \
            cp16(sm0 + TILE_B + so_, gp1 + go_); \
        } \
        cp_commit(); \
    } while (0)

    #define FLOADB(s, ksv) do { \
        _Pragma("unroll") \
        for (int nt_ = 0; nt_ < 8; nt_++) { \
            const int col_ = wn * 64 + nt_ * 8 + gid; \
            const int o_ = col_ * (int)RBYTES + (ksv) * 32 + tg * 4; \
            bv[s][nt_][0] = *(const uint32_t*)(pB + o_); \
            bv[s][nt_][1] = *(const uint32_t*)(pB + o_ + 16); \
        } \
    } while (0)
    #define FLOADA(s, ksv) do { \
        _Pragma("unroll") \
        for (int mt_ = 0; mt_ < 4; mt_++) { \
            const int r0_ = (wm * 64 + mt_ * 16 + gid) * (int)RBYTES + (ksv) * 32 + tg * 4; \
            const int r1_ = r0_ + 8 * (int)RBYTES; \
            av[s][mt_][0] = *(const uint32_t*)(pA + r0_); \
            av[s][mt_][1] = *(const uint32_t*)(pA + r1_); \
            av[s][mt_][2] = *(const uint32_t*)(pA + r0_ + 16); \
            av[s][mt_][3] = *(const uint32_t*)(pA + r1_ + 16); \
        } \
    } while (0)

    float acc[4][8][4];
    #pragma unroll
    for (int mt = 0; mt < 4; mt++)
        #pragma unroll
        for (int nt = 0; nt < 8; nt++)
            #pragma unroll
            for (int c = 0; c < 4; c++) acc[mt][nt][c] = 0.f;

    const int nT = KK / 64;

    LOADCHUNK(0, 0);

    for (int t = 0; t < nT; t++) {
        if (t + 1 < nT) LOADCHUNK(t + 1, (t + 1) & 1);
        if (t + 1 < nT) cp_wait1(); else cp_wait0();
        __syncthreads();

        const char* stage = smem + (uint32_t)(t & 1) * STAGE_B;
        const char* pA = stage;
        const char* pB = stage + TILE_B;

        uint32_t av[2][4][4];
        uint32_t bv[2][8][2];

        FLOADB(0, 0);
        FLOADA(0, 0);
        #pragma unroll
        for (int ks = 0; ks < 4; ks++) {
            const int cs = ks & 1;
            if (ks < 3) {
                FLOADB(cs ^ 1, ks + 1);
                FLOADA(cs ^ 1, ks + 1);
            }
            #pragma unroll
            for (int mt = 0; mt < 4; mt++)
                #pragma unroll
                for (int nt = 0; nt < 8; nt++)
                    mma_f16(acc[mt][nt], av[cs][mt], bv[cs][nt]);
        }
        __syncthreads();
    }
    #undef LOADCHUNK
    #undef FLOADA
    #undef FLOADB

    #pragma unroll
    for (int nt = 0; nt < 8; nt++) {
        const int col = bn0 + wn * 64 + nt * 8 + tg * 2;
        const float2 bvv = *(const float2*)(bias + col);
        #pragma unroll
        for (int mt = 0; mt < 4; mt++) {
            const int r0 = bm0 + wm * 64 + mt * 16 + gid;
            *(float2*)(C + (size_t)r0 * N + col) =
                make_float2(acc[mt][nt][0] + bvv.x, acc[mt][nt][1] + bvv.y);
            *(float2*)(C + (size_t)(r0 + 8) * N + col) =
                make_float2(acc[mt][nt][2] + bvv.x, acc[mt][nt][3] + bvv.y);
        }
    }
}

// ---------------------------------------------------------------------------
// Fused weight transposes only (x no longer converted):
//   blocks [0, NB_W1)       : qkv_w transpose+convert -> w1
//   blocks [NB_W1, +NB_W2)  : proj_w transpose+convert -> w2
// ---------------------------------------------------------------------------
#define NTK   (KK / 32)                      // 16
#define NB_W1 (NTK * ((3 * CCX) / 32))       // 768
#define NB_W2 (NTK * (CCX / 32))             // 256

__global__ __launch_bounds__(256)
void conv_w(const float* __restrict__ qkv_w,
            const float* __restrict__ proj_w,
            __half* __restrict__ w1,
            __half* __restrict__ w2)
{
    __shared__ float t[32][33];
    const int bid = blockIdx.x;
    const int tid = threadIdx.x;
    const int tx = tid & 31;
    const int ty = tid >> 5;

    const float* w;
    __half* o;
    int tileid, Ndim;
    if (bid < NB_W1) {
        tileid = bid;
        w = qkv_w; o = w1; Ndim = 3 * CCX;
    } else {
        tileid = bid - NB_W1;
        w = proj_w; o = w2; Ndim = CCX;
    }
    const int k0 = (tileid % NTK) * 32;
    const int n0 = (tileid / NTK) * 32;

    #pragma unroll
    for (int r = 0; r < 32; r += 8)
        t[ty + r][tx] = w[(size_t)(k0 + ty + r) * Ndim + n0 + tx];
    __syncthreads();
    #pragma unroll
    for (int r = 0; r < 32; r += 8) {
        float v = t[tx][ty + r];
        o[(size_t)(n0 + ty + r) * KK + k0 + tx] = __float2half_rn(v);
    }
}

// ---------------------------------------------------------------------------
// Neighborhood attention (R13 config): thread-per-l; fp16 q/k/v; LT=128.
// ---------------------------------------------------------------------------
#define LT 128
#define WR (LT + KWX - 1)       // 140
#define SSTR2 34                // halfs per row (68 B)

__global__ __launch_bounds__(128)
void natten1d_kernel(const float* __restrict__ rpb)
{
    __shared__ __half sk[WR * SSTR2];
    __shared__ __half sv[WR * SSTR2];
    __shared__ float srpb[NRPBX];

    const int tid  = threadIdx.x;
    const int warp = tid >> 5;
    const int lane = tid & 31;
    const int l0 = blockIdx.x * LT;
    const int h  = blockIdx.y;
    const int b  = blockIdx.z;
    const int base = l0 - KHX;

    const __half* qb = g_qkvh + (size_t)b * LLX * (3 * CCX) + h * HDX;
    const __half* kb = qb + CCX;
    const __half* vb = qb + 2 * CCX;

    if (tid < NRPBX) srpb[tid] = rpb[h * NRPBX + tid];

    for (int r = warp; r < WR; r += 4) {
        const int gr = base + r;
        if (gr >= 0 && gr < LLX) {
            sk[r * SSTR2 + lane] = kb[(size_t)gr * (3 * CCX) + lane];
            sv[r * SSTR2 + lane] = vb[(size_t)gr * (3 * CCX) + lane];
        }
    }
    __syncthreads();

    const int l = l0 + tid;
    int ni = l - KHX;
    if (ni < 0) ni = 0;
    if (ni > LLX - KWX) ni = LLX - KWX;
    const int roff = ni - l + (KWX - 1);
    const int s0 = ni - base;

    const float scale = 0.17677669529663687f;
    float q[HDX];
    {
        const __half2* qp = (const __half2*)(qb + (size_t)l * (3 * CCX));
        #pragma unroll
        for (int d2 = 0; d2 < HDX / 2; d2++) {
            float2 v = __half22float2(qp[d2]);
            q[2 * d2 + 0] = v.x * scale;
            q[2 * d2 + 1] = v.y * scale;
        }
    }

    float sc[KWX];
    float smax = -1e30f;
    #pragma unroll
    for (int j = 0; j < KWX; j++) {
        const __half2* kr = (const __half2*)&sk[(s0 + j) * SSTR2];
        float s = 0.f;
        #pragma unroll
        for (int d2 = 0; d2 < HDX / 2; d2++) {
            float2 kv = __half22float2(kr[d2]);
            s = fmaf(q[2 * d2 + 0], kv.x, s);
            s = fmaf(q[2 * d2 + 1], kv.y, s);
        }
        s += srpb[roff + j];
        sc[j] = s;
        smax = fmaxf(smax, s);
    }
    float ssum = 0.f;
    #pragma unroll
    for (int j = 0; j < KWX; j++) {
        sc[j] = __expf(sc[j] - smax);
        ssum += sc[j];
    }
    const float inv = 1.f / ssum;

    float acc[HDX];
    #pragma unroll
    for (int d = 0; d < HDX; d++) acc[d] = 0.f;
    #pragma unroll
    for (int j = 0; j < KWX; j++) {
        const __half2* vr = (const __half2*)&sv[(s0 + j) * SSTR2];
        const float p = sc[j];
        #pragma unroll
        for (int d2 = 0; d2 < HDX / 2; d2++) {
            float2 vv = __half22float2(vr[d2]);
            acc[2 * d2 + 0] = fmaf(p, vv.x, acc[2 * d2 + 0]);
            acc[2 * d2 + 1] = fmaf(p, vv.y, acc[2 * d2 + 1]);
        }
    }

    __half* oh = g_at + (size_t)(b * LLX + l) * CCX + h * HDX;
    #pragma unroll
    for (int d2 = 0; d2 < HDX; d2 += 2) {
        __half2 hp = __floats2half2_rn(acc[d2] * inv, acc[d2 + 1] * inv);
        *(uint32_t*)(oh + d2) = *(uint32_t*)&hp;
    }
}

// ---------------------------------------------------------------------------
extern "C" void kernel_launch(void* const* d_in, const int* in_sizes, int n_in,
                              void* d_out, int out_size)
{
    const float* x      = (const float*)d_in[0];
    const float* qkv_w  = (const float*)d_in[1];
    const float* qkv_b  = (const float*)d_in[2];
    const float* rpb    = (const float*)d_in[3];
    const float* proj_w = (const float*)d_in[4];
    const float* proj_b = (const float*)d_in[5];
    float* out = (float*)d_out;

    __half *qkvh, *at, *w1, *w2;
    cudaGetSymbolAddress((void**)&qkvh, g_qkvh);
    cudaGetSymbolAddress((void**)&at,   g_at);
    cudaGetSymbolAddress((void**)&w1,   g_w1);
    cudaGetSymbolAddress((void**)&w2,   g_w2);

    cudaFuncSetAttribute(gemm1_f32a,
                         cudaFuncAttributeMaxDynamicSharedMemorySize, SMEM1);
    cudaFuncSetAttribute(fp16_gemm_f32out,
                         cudaFuncAttributeMaxDynamicSharedMemorySize, GEMM_SMEM);

    // 1) weight transposes (x no longer pre-converted)
    conv_w<<<NB_W1 + NB_W2, 256>>>(qkv_w, proj_w, w1, w2);

    // 2) QKV GEMM: fp32 x read directly -> g_qkvh (fp16)
    {
        dim3 grid((3 * CCX) / 128, MLX / 128);
        gemm1_f32a<<<grid, 128, SMEM1>>>(x, w1, qkv_b, qkvh, 3 * CCX);
    }

    // 3) attention (fp16 in, fp16 out)
    {
        dim3 grid(LLX / LT, HHX, BBX);
        natten1d_kernel<<<grid, 128>>>(rpb);
    }

    // 4) proj GEMM: [16384,512] x [512,512]^T -> out (fp32)
    {
        dim3 grid(CCX / 128, MLX / 128);
        fp16_gemm_f32out<<<grid, 128, GEMM_SMEM>>>(at, w2, proj_b, out, CCX);
    }
}

// round 17
// speedup vs baseline: 1.1358x; 1.1358x over previous
#include <cuda_runtime.h>
#include <cuda_fp16.h>
#include <cstdint>
#include <math.h>

// Problem constants
#define BBX 4
#define LLX 4096
#define CCX 512
#define HHX 16
#define HDX 32
#define KWX 13
#define KHX 6
#define NRPBX 25
#define MLX (BBX*LLX)          // 16384
#define KK  512

// ---------------------------------------------------------------------------
// Global scratch
// ---------------------------------------------------------------------------
__device__ __half g_qkvh[(size_t)MLX * (3 * CCX)];     // qkv fp16
__device__ __half g_xa[(size_t)MLX * CCX];             // x as fp16
__device__ __half g_at[(size_t)MLX * CCX];             // attn out fp16
__device__ __half g_w1[(size_t)(3*CCX) * CCX];         // qkv_w^T [1536,512] fp16
__device__ __half g_w2[(size_t)CCX * CCX];             // proj_w^T [512,512] fp16

// ---------------------------------------------------------------------------
// Helpers
// ---------------------------------------------------------------------------
__device__ __forceinline__ uint32_t sptr(const void* p) {
    return (uint32_t)__cvta_generic_to_shared(p);
}
__device__ __forceinline__ void cp16(uint32_t s, const void* g) {
    asm volatile("cp.async.cg.shared.global [%0], [%1], 16;\n" :: "r"(s), "l"(g));
}
__device__ __forceinline__ void cp_commit() {
    asm volatile("cp.async.commit_group;\n" ::: "memory");
}
__device__ __forceinline__ void cp_wait0() {
    asm volatile("cp.async.wait_group 0;\n" ::: "memory");
}
__device__ __forceinline__ void cp_wait1() {
    asm volatile("cp.async.wait_group 1;\n" ::: "memory");
}
__device__ __forceinline__ void mma_f16(float* c, const uint32_t* a, const uint32_t* b) {
    asm volatile(
        "mma.sync.aligned.m16n8k16.row.col.f32.f16.f16.f32 "
        "{%0,%1,%2,%3}, {%4,%5,%6,%7}, {%8,%9}, {%0,%1,%2,%3};\n"
        : "+f"(c[0]), "+f"(c[1]), "+f"(c[2]), "+f"(c[3])
        : "r"(a[0]), "r"(a[1]), "r"(a[2]), "r"(a[3]), "r"(b[0]), "r"(b[1]));
}

// ---------------------------------------------------------------------------
// fp16 GEMM (R13/R15 config — proven plateau): C = A x B^T + bias
// 128x128 CTA tile, 128 threads (4 warps 2x2, warp tile 64x64),
// BK=64 (8 chunks), 2-stage cp.async ring, register-double-buffered frags.
// ---------------------------------------------------------------------------
#define RBYTES 144                   // bytes per 64-fp16 row (128 + 16 pad)
#define TILE_B (128u * RBYTES)       // 18432 B
#define STAGE_B (2u * TILE_B)        // 36864 B  (A, B)
#define GEMM_SMEM (2u * STAGE_B)     // 73728 B

template <typename OutT>
__global__ __launch_bounds__(128, 2)
void fp16_gemm(const __half* __restrict__ A, const __half* __restrict__ B,
               const float* __restrict__ bias, OutT* __restrict__ C, int N)
{
    extern __shared__ char smem[];

    const int tid  = threadIdx.x;
    const int warp = tid >> 5;
    const int lane = tid & 31;
    const int wm   = warp & 1;
    const int wn   = warp >> 1;
    const int gid  = lane >> 2;
    const int tg   = lane & 3;

    const int bm0 = blockIdx.y * 128;
    const int bn0 = blockIdx.x * 128;

    const __half* t0 = A + (size_t)bm0 * KK;
    const __half* t1 = B + (size_t)bn0 * KK;
    const uint32_t sbase = sptr(smem);

    #define LOADCHUNK(c, bufb) do { \
        const uint32_t sm0 = sbase + (bufb) * STAGE_B; \
        const __half* gp0 = t0 + (c) * 64; \
        const __half* gp1 = t1 + (c) * 64; \
        _Pragma("unroll") \
        for (int i_ = 0; i_ < 8; i_++) { \
            int u_ = i_ * 128 + tid; \
            int row_ = u_ >> 3; \
            int c16_ = u_ & 7; \
            uint32_t so_ = (uint32_t)(row_ * RBYTES + c16_ * 16); \
            size_t go_ = (size_t)row_ * KK + c16_ * 8; \
            cp16(sm0 + so_,          gp0 + go_); \
            cp16(sm0 + TILE_B + so_, gp1 + go_); \
        } \
        cp_commit(); \
    } while (0)

    #define FLOADB(s, ksv) do { \
        _Pragma("unroll") \
        for (int nt_ = 0; nt_ < 8; nt_++) { \
            const int col_ = wn * 64 + nt_ * 8 + gid; \
            const int o_ = col_ * RBYTES + (ksv) * 32 + tg * 4; \
            bv[s][nt_][0] = *(const uint32_t*)(pB + o_); \
            bv[s][nt_][1] = *(const uint32_t*)(pB + o_ + 16); \
        } \
    } while (0)
    #define FLOADA(s, ksv) do { \
        _Pragma("unroll") \
        for (int mt_ = 0; mt_ < 4; mt_++) { \
            const int r0_ = (wm * 64 + mt_ * 16 + gid) * RBYTES + (ksv) * 32 + tg * 4; \
            const int r1_ = r0_ + 8 * RBYTES; \
            av[s][mt_][0] = *(const uint32_t*)(pA + r0_); \
            av[s][mt_][1] = *(const uint32_t*)(pA + r1_); \
            av[s][mt_][2] = *(const uint32_t*)(pA + r0_ + 16); \
            av[s][mt_][3] = *(const uint32_t*)(pA + r1_ + 16); \
        } \
    } while (0)

    float acc[4][8][4];
    #pragma unroll
    for (int mt = 0; mt < 4; mt++)
        #pragma unroll
        for (int nt = 0; nt < 8; nt++)
            #pragma unroll
            for (int c = 0; c < 4; c++) acc[mt][nt][c] = 0.f;

    const int nT = KK / 64;          // 8 chunks

    LOADCHUNK(0, 0);

    for (int t = 0; t < nT; t++) {
        if (t + 1 < nT) LOADCHUNK(t + 1, (t + 1) & 1);
        if (t + 1 < nT) cp_wait1(); else cp_wait0();
        __syncthreads();

        const char* stage = smem + (uint32_t)(t & 1) * STAGE_B;
        const char* pA = stage;
        const char* pB = stage + TILE_B;

        uint32_t av[2][4][4];
        uint32_t bv[2][8][2];

        FLOADB(0, 0);
        FLOADA(0, 0);
        #pragma unroll
        for (int ks = 0; ks < 4; ks++) {
            const int cs = ks & 1;
            if (ks < 3) {
                FLOADB(cs ^ 1, ks + 1);
                FLOADA(cs ^ 1, ks + 1);
            }
            #pragma unroll
            for (int mt = 0; mt < 4; mt++)
                #pragma unroll
                for (int nt = 0; nt < 8; nt++)
                    mma_f16(acc[mt][nt], av[cs][mt], bv[cs][nt]);
        }
        __syncthreads();
    }
    #undef LOADCHUNK
    #undef FLOADA
    #undef FLOADB

    // epilogue
    #pragma unroll
    for (int nt = 0; nt < 8; nt++) {
        const int col = bn0 + wn * 64 + nt * 8 + tg * 2;
        const float2 bvv = *(const float2*)(bias + col);
        #pragma unroll
        for (int mt = 0; mt < 4; mt++) {
            const int r0 = bm0 + wm * 64 + mt * 16 + gid;
            const float x0 = acc[mt][nt][0] + bvv.x;
            const float y0 = acc[mt][nt][1] + bvv.y;
            const float x1 = acc[mt][nt][2] + bvv.x;
            const float y1 = acc[mt][nt][3] + bvv.y;
            if constexpr (sizeof(OutT) == 4) {
                *(float2*)((float*)C + (size_t)r0 * N + col)       = make_float2(x0, y0);
                *(float2*)((float*)C + (size_t)(r0 + 8) * N + col) = make_float2(x1, y1);
            } else {
                __half2 h0 = __floats2half2_rn(x0, y0);
                __half2 h1 = __floats2half2_rn(x1, y1);
                *(__half2*)((__half*)C + (size_t)r0 * N + col)       = h0;
                *(__half2*)((__half*)C + (size_t)(r0 + 8) * N + col) = h1;
            }
        }
    }
}

// ---------------------------------------------------------------------------
// Fused conversions (R15): x -> fp16, both weight transposes, one launch.
// ---------------------------------------------------------------------------
#define NB_X  ((MLX * CCX / 4) / 256)        // 8192
#define NTK   (KK / 32)                      // 16
#define NB_W1 (NTK * ((3 * CCX) / 32))       // 768
#define NB_W2 (NTK * (CCX / 32))             // 256

__global__ __launch_bounds__(256)
void conv_fused(const float* __restrict__ x,
                const float* __restrict__ qkv_w,
                const float* __restrict__ proj_w,
                __half* __restrict__ xa,
                __half* __restrict__ w1,
                __half* __restrict__ w2)
{
    const int bid = blockIdx.x;
    const int tid = threadIdx.x;

    if (bid < NB_X) {
        const int i = bid * 256 + tid;
        float4 v = ((const float4*)x)[i];
        __half2 p0 = __floats2half2_rn(v.x, v.y);
        __half2 p1 = __floats2half2_rn(v.z, v.w);
        ((uint2*)xa)[i] = make_uint2(*(uint32_t*)&p0, *(uint32_t*)&p1);
        return;
    }

    __shared__ float t[32][33];
    const int tx = tid & 31;
    const int ty = tid >> 5;

    const float* w;
    __half* o;
    int tileid, Ndim;
    if (bid < NB_X + NB_W1) {
        tileid = bid - NB_X;
        w = qkv_w; o = w1; Ndim = 3 * CCX;
    } else {
        tileid = bid - NB_X - NB_W1;
        w = proj_w; o = w2; Ndim = CCX;
    }
    const int k0 = (tileid % NTK) * 32;
    const int n0 = (tileid / NTK) * 32;

    #pragma unroll
    for (int r = 0; r < 32; r += 8)
        t[ty + r][tx] = w[(size_t)(k0 + ty + r) * Ndim + n0 + tx];
    __syncthreads();
    #pragma unroll
    for (int r = 0; r < 32; r += 8) {
        float v = t[tx][ty + r];
        o[(size_t)(n0 + ty + r) * KK + k0 + tx] = __float2half_rn(v);
    }
}

// ---------------------------------------------------------------------------
// Neighborhood attention v2: fully coalesced global access.
//  - q staged to smem coalesced (row-per-warp, like k/v)
//  - output staged through smem (reusing sq) and stored coalesced
// Thread-per-l math unchanged (bit-identical results).
// ---------------------------------------------------------------------------
#define LT 128
#define WR (LT + KWX - 1)       // 140
#define SSTR2 34                // halfs per row (68 B); word stride 17 (odd)

__global__ __launch_bounds__(128)
void natten1d_kernel(const float* __restrict__ rpb)
{
    __shared__ __half sk[WR * SSTR2];
    __shared__ __half sv[WR * SSTR2];
    __shared__ __half sq[LT * SSTR2];
    __shared__ float srpb[NRPBX];

    const int tid  = threadIdx.x;
    const int warp = tid >> 5;
    const int lane = tid & 31;
    const int l0 = blockIdx.x * LT;
    const int h  = blockIdx.y;
    const int b  = blockIdx.z;
    const int base = l0 - KHX;

    const __half* qb = g_qkvh + (size_t)b * LLX * (3 * CCX) + h * HDX;
    const __half* kb = qb + CCX;
    const __half* vb = qb + 2 * CCX;

    if (tid < NRPBX) srpb[tid] = rpb[h * NRPBX + tid];

    // coalesced staging: each warp loads one row (64 B) per iteration
    for (int r = warp; r < WR; r += 4) {
        const int gr = base + r;
        if (gr >= 0 && gr < LLX) {
            sk[r * SSTR2 + lane] = kb[(size_t)gr * (3 * CCX) + lane];
            sv[r * SSTR2 + lane] = vb[(size_t)gr * (3 * CCX) + lane];
        }
    }
    for (int r = warp; r < LT; r += 4) {
        sq[r * SSTR2 + lane] = qb[(size_t)(l0 + r) * (3 * CCX) + lane];
    }
    __syncthreads();

    const int l = l0 + tid;
    int ni = l - KHX;
    if (ni < 0) ni = 0;
    if (ni > LLX - KWX) ni = LLX - KWX;
    const int roff = ni - l + (KWX - 1);
    const int s0 = ni - base;

    const float scale = 0.17677669529663687f;
    float q[HDX];
    {
        const __half2* qp = (const __half2*)&sq[tid * SSTR2];
        #pragma unroll
        for (int d2 = 0; d2 < HDX / 2; d2++) {
            float2 v = __half22float2(qp[d2]);
            q[2 * d2 + 0] = v.x * scale;
            q[2 * d2 + 1] = v.y * scale;
        }
    }

    float sc[KWX];
    float smax = -1e30f;
    #pragma unroll
    for (int j = 0; j < KWX; j++) {
        const __half2* kr = (const __half2*)&sk[(s0 + j) * SSTR2];
        float s = 0.f;
        #pragma unroll
        for (int d2 = 0; d2 < HDX / 2; d2++) {
            float2 kv = __half22float2(kr[d2]);
            s = fmaf(q[2 * d2 + 0], kv.x, s);
            s = fmaf(q[2 * d2 + 1], kv.y, s);
        }
        s += srpb[roff + j];
        sc[j] = s;
        smax = fmaxf(smax, s);
    }
    float ssum = 0.f;
    #pragma unroll
    for (int j = 0; j < KWX; j++) {
        sc[j] = __expf(sc[j] - smax);
        ssum += sc[j];
    }
    const float inv = 1.f / ssum;

    float acc[HDX];
    #pragma unroll
    for (int d = 0; d < HDX; d++) acc[d] = 0.f;
    #pragma unroll
    for (int j = 0; j < KWX; j++) {
        const __half2* vr = (const __half2*)&sv[(s0 + j) * SSTR2];
        const float p = sc[j];
        #pragma unroll
        for (int d2 = 0; d2 < HDX / 2; d2++) {
            float2 vv = __half22float2(vr[d2]);
            acc[2 * d2 + 0] = fmaf(p, vv.x, acc[2 * d2 + 0]);
            acc[2 * d2 + 1] = fmaf(p, vv.y, acc[2 * d2 + 1]);
        }
    }

    // stage output into sq (q already consumed), then coalesced store
    __syncthreads();
    {
        __half2* op = (__half2*)&sq[tid * SSTR2];
        #pragma unroll
        for (int d2 = 0; d2 < HDX / 2; d2++)
            op[d2] = __floats2half2_rn(acc[2 * d2] * inv, acc[2 * d2 + 1] * inv);
    }
    __syncthreads();
    {
        __half* ob = g_at + (size_t)(b * LLX + l0) * CCX + h * HDX;
        // 128 rows x 16 half2; consecutive tid -> consecutive columns (64 B/16 thr)
        #pragma unroll
        for (int it = 0; it < (LT * 16) / 128; it++) {
            const int idx = it * 128 + tid;
            const int row = idx >> 4;
            const int c   = idx & 15;
            *(__half2*)(ob + (size_t)row * CCX + c * 2) =
                *(const __half2*)&sq[row * SSTR2 + c * 2];
        }
    }
}

// ---------------------------------------------------------------------------
extern "C" void kernel_launch(void* const* d_in, const int* in_sizes, int n_in,
                              void* d_out, int out_size)
{
    const float* x      = (const float*)d_in[0];
    const float* qkv_w  = (const float*)d_in[1];
    const float* qkv_b  = (const float*)d_in[2];
    const float* rpb    = (const float*)d_in[3];
    const float* proj_w = (const float*)d_in[4];
    const float* proj_b = (const float*)d_in[5];
    float* out = (float*)d_out;

    __half *qkvh, *xa, *at, *w1, *w2;
    cudaGetSymbolAddress((void**)&qkvh, g_qkvh);
    cudaGetSymbolAddress((void**)&xa,   g_xa);
    cudaGetSymbolAddress((void**)&at,   g_at);
    cudaGetSymbolAddress((void**)&w1,   g_w1);
    cudaGetSymbolAddress((void**)&w2,   g_w2);

    cudaFuncSetAttribute(fp16_gemm<__half>,
                         cudaFuncAttributeMaxDynamicSharedMemorySize, GEMM_SMEM);
    cudaFuncSetAttribute(fp16_gemm<float>,
                         cudaFuncAttributeMaxDynamicSharedMemorySize, GEMM_SMEM);

    // 1) fused conversions
    conv_fused<<<NB_X + NB_W1 + NB_W2, 256>>>(x, qkv_w, proj_w, xa, w1, w2);

    // 2) QKV GEMM: [16384,512] x [1536,512]^T -> g_qkvh (fp16)
    {
        dim3 grid((3 * CCX) / 128, MLX / 128);
        fp16_gemm<__half><<<grid, 128, GEMM_SMEM>>>(xa, w1, qkv_b, qkvh, 3 * CCX);
    }

    // 3) attention (coalesced q/out staging)
    {
        dim3 grid(LLX / LT, HHX, BBX);
        natten1d_kernel<<<grid, 128>>>(rpb);
    }

    // 4) proj GEMM: [16384,512] x [512,512]^T -> out (fp32)
    {
        dim3 grid(CCX / 128, MLX / 128);
        fp16_gemm<float><<<grid, 128, GEMM_SMEM>>>(at, w2, proj_b, out, CCX);
    }
}